// round 17
// baseline (speedup 1.0000x reference)
#include <cuda_runtime.h>
#include <cuda_fp16.h>
#include <cuda_bf16.h>
#include <cstdint>

#define BATCH 4
#define CDIM  768
#define TDIM  2048
#define NHEAD 12
#define HDIM  64
#define QKVROWS (3 * CDIM)

// ---------------------------------------------------------------------------
// Device scratch (all activations fp16, plain [row][col] half layouts)
// ---------------------------------------------------------------------------
__device__ __half g_qt [(size_t)BATCH * NHEAD * TDIM * HDIM]; // Q^T [b,h][t][d]
__device__ __half g_kt [(size_t)BATCH * NHEAD * TDIM * HDIM]; // K^T [b,h][s][d]
__device__ __half g_vh [(size_t)BATCH * CDIM * TDIM];         // V   [b][d_glob][s]
__device__ __half g_oh [(size_t)BATCH * CDIM * TDIM];         // o   [b][c][t]
__device__ __half g_xh [(size_t)BATCH * CDIM * TDIM];         // x   [b][c][t]
__device__ __half g_wqh[(size_t)QKVROWS * CDIM];              // Wqkv fp16 [M][K]
__device__ __half g_woh[(size_t)CDIM * CDIM];                 // Wout fp16 [M][K]

// pack two f32 into fp16x2: lo -> lower half, hi -> upper half (RN)
__device__ __forceinline__ uint32_t pack_half2(float lo, float hi) {
    uint32_t r;
    asm("cvt.rn.f16x2.f32 %0, %1, %2;" : "=r"(r) : "f"(hi), "f"(lo));
    return r;
}

// p2 = ex2.approx.f16x2( s2 * sc2 + b2 )
__device__ __forceinline__ uint32_t h2_fma_ex2(uint32_t s2, uint32_t sc2x2, uint32_t b2) {
    uint32_t r;
    asm("{ .reg .b32 t;\n"
        "  fma.rn.f16x2 t, %1, %2, %3;\n"
        "  ex2.approx.f16x2 %0, t; }\n"
        : "=r"(r) : "r"(s2), "r"(sc2x2), "r"(b2));
    return r;
}

__device__ __forceinline__ void mma_fp16(float* c, const uint32_t* a, const uint32_t* b) {
    asm volatile(
        "mma.sync.aligned.m16n8k16.row.col.f32.f16.f16.f32 "
        "{%0,%1,%2,%3}, {%4,%5,%6,%7}, {%8,%9}, {%0,%1,%2,%3};\n"
        : "+f"(c[0]), "+f"(c[1]), "+f"(c[2]), "+f"(c[3])
        : "r"(a[0]), "r"(a[1]), "r"(a[2]), "r"(a[3]), "r"(b[0]), "r"(b[1]));
}

__device__ __forceinline__ void ldsm_x4(uint32_t& r0, uint32_t& r1, uint32_t& r2,
                                        uint32_t& r3, uint32_t addr) {
    asm volatile("ldmatrix.sync.aligned.m8n8.x4.shared.b16 {%0,%1,%2,%3}, [%4];"
                 : "=r"(r0), "=r"(r1), "=r"(r2), "=r"(r3) : "r"(addr));
}
__device__ __forceinline__ void ldsm_x4_t(uint32_t& r0, uint32_t& r1, uint32_t& r2,
                                          uint32_t& r3, uint32_t addr) {
    asm volatile("ldmatrix.sync.aligned.m8n8.x4.trans.shared.b16 {%0,%1,%2,%3}, [%4];"
                 : "=r"(r0), "=r"(r1), "=r"(r2), "=r"(r3) : "r"(addr));
}

__device__ __forceinline__ uint32_t smem_u32(const void* p) {
    return (uint32_t)__cvta_generic_to_shared(p);
}

__device__ __forceinline__ void cp_async16(uint32_t dst, const void* src) {
    asm volatile("cp.async.cg.shared.global [%0], [%1], 16;\n"
                 :: "r"(dst), "l"(src));
}
#define CP_COMMIT() asm volatile("cp.async.commit_group;\n")

// ---------------------------------------------------------------------------
// Pack: f32 -> fp16 elementwise (used for weights and x)
// ---------------------------------------------------------------------------
__global__ __launch_bounds__(256)
void pack_h_kernel(const float* __restrict__ in, __half* __restrict__ out, int n)
{
    int i = (blockIdx.x * 256 + threadIdx.x) * 4;
    if (i < n) {
        float4 v = *reinterpret_cast<const float4*>(in + i);
        uint2 w = make_uint2(pack_half2(v.x, v.y), pack_half2(v.z, v.w));
        *reinterpret_cast<uint2*>(out + i) = w;
    }
}

// ---------------------------------------------------------------------------
// fp16 GEMM with ldmatrix fragments.
// 128x128 tile, 128 thr (2x2 warps, 64x64 warp tile), kTile=32, cp.async DB.
// A: fp16 [M][K], smem [m][k] pitch 40 halves. B: fp16 [K][N], smem [k][n]
// pitch 136 halves. A frags: ldmatrix.x4; B frags: ldmatrix.x4.trans.
// MODE 0: C = f32 + bias. MODE 1: Q->qT, K->kT, V->vh (all fp16).
// ---------------------------------------------------------------------------
#define GA_H (128 * 40)
#define GB_H (32 * 136)
#define GEMM_SMEM_BYTES ((2 * GA_H + 2 * GB_H) * 2)

template<int MODE>
__global__ __launch_bounds__(128, 2)
void gemm_fp16_ldsm(const __half* __restrict__ Ah,
                    const __half* __restrict__ Bh,
                    const float* __restrict__ bias,
                    float* __restrict__ Cmat,
                    __half* __restrict__ qroot,
                    __half* __restrict__ kroot,
                    __half* __restrict__ vroot,
                    int M, int N, int K)
{
    extern __shared__ __half gsmh[];

    const __half* Bp = Bh + (size_t)blockIdx.z * (size_t)K * N;
    float*        Cp = (MODE == 0) ? Cmat + (size_t)blockIdx.z * (size_t)M * N : nullptr;

    const int tid  = threadIdx.x;
    const int lane = tid & 31;
    const int warp = tid >> 5;
    const int g    = lane >> 2;
    const int tig  = lane & 3;
    const int wm   = warp >> 1;
    const int wn   = warp & 1;
    const int row0 = blockIdx.y * 128;
    const int col0 = blockIdx.x * 128;

    const uint32_t sbase = smem_u32(gsmh);
    const int l16 = lane & 15;       // ldmatrix row select
    const int lhi = lane >> 4;       // ldmatrix 8-col half select

    float acc[4][8][4];
    #pragma unroll
    for (int i = 0; i < 4; i++)
        #pragma unroll
        for (int j = 0; j < 8; j++)
            #pragma unroll
            for (int r = 0; r < 4; r++) acc[i][j][r] = 0.0f;

    const int KT = K >> 5;

    auto issue = [&](int s) {
        const int k0 = s * 32;
        const uint32_t abase = sbase + (unsigned)((s & 1) * GA_H) * 2u;
        const uint32_t bbase = sbase + (unsigned)(2 * GA_H + (s & 1) * GB_H) * 2u;
        #pragma unroll
        for (int l = 0; l < 4; l++) {          // A: 128 m x 4 chunks (8 halves)
            int lin = tid + l * 128;
            int m   = lin >> 2;
            int c   = lin & 3;
            cp_async16(abase + (unsigned)(m * 40 + c * 8) * 2u,
                       Ah + (size_t)(row0 + m) * K + k0 + c * 8);
        }
        #pragma unroll
        for (int l = 0; l < 4; l++) {          // B: 32 k x 16 chunks (8 halves)
            int lin = tid + l * 128;
            int k   = lin >> 4;
            int c   = lin & 15;
            cp_async16(bbase + (unsigned)(k * 136 + c * 8) * 2u,
                       Bp + (size_t)(k0 + k) * N + col0 + c * 8);
        }
        CP_COMMIT();
    };

    issue(0);
    if (KT > 1) issue(1);

    for (int kt = 0; kt < KT; kt++) {
        const int buf = kt & 1;
        if (kt + 1 < KT) asm volatile("cp.async.wait_group 1;\n");
        else             asm volatile("cp.async.wait_group 0;\n");
        __syncthreads();

        const uint32_t abase = sbase + (unsigned)(buf * GA_H) * 2u;
        const uint32_t bbase = sbase + (unsigned)(2 * GA_H + buf * GB_H) * 2u;

        #pragma unroll
        for (int ks = 0; ks < 2; ks++) {
            uint32_t af[4][4];
            uint32_t bf[8][2];
            #pragma unroll
            for (int mi = 0; mi < 4; mi++) {
                int m = wm * 64 + mi * 16 + l16;
                ldsm_x4(af[mi][0], af[mi][1], af[mi][2], af[mi][3],
                        abase + (unsigned)(m * 40 + ks * 16 + lhi * 8) * 2u);
            }
            #pragma unroll
            for (int p = 0; p < 4; p++) {
                int krow = ks * 16 + l16;
                int n    = wn * 64 + p * 16 + lhi * 8;
                // trans: r0=b0(2p), r1=b1(2p), r2=b0(2p+1), r3=b1(2p+1)
                ldsm_x4_t(bf[2 * p][0], bf[2 * p][1], bf[2 * p + 1][0], bf[2 * p + 1][1],
                          bbase + (unsigned)(krow * 136 + n) * 2u);
            }
            #pragma unroll
            for (int mi = 0; mi < 4; mi++)
                #pragma unroll
                for (int ni = 0; ni < 8; ni++)
                    mma_fp16(acc[mi][ni], af[mi], bf[ni]);
        }

        __syncthreads();
        if (kt + 2 < KT) issue(kt + 2);
    }

    #pragma unroll
    for (int mi = 0; mi < 4; mi++) {
        int r0 = row0 + wm * 64 + mi * 16 + g;
        float b0 = bias[r0];
        float b1 = bias[r0 + 8];
        if (MODE == 0) {
            #pragma unroll
            for (int ni = 0; ni < 8; ni++) {
                int cc = col0 + wn * 64 + ni * 8 + tig * 2;
                *reinterpret_cast<float2*>(Cp + (size_t)r0 * N + cc) =
                    make_float2(acc[mi][ni][0] + b0, acc[mi][ni][1] + b0);
                *reinterpret_cast<float2*>(Cp + (size_t)(r0 + 8) * N + cc) =
                    make_float2(acc[mi][ni][2] + b1, acc[mi][ni][3] + b1);
            }
        } else {
            const int cls = r0 / CDIM;           // 0=Q, 1=K, 2=V
            if (cls == 2) {
                __half* Vp = vroot + (size_t)blockIdx.z * CDIM * TDIM;
                #pragma unroll
                for (int ni = 0; ni < 8; ni++) {
                    int cc = col0 + wn * 64 + ni * 8 + tig * 2;
                    __half* vp = Vp + (size_t)(r0 - 2 * CDIM) * N + cc;
                    *reinterpret_cast<uint32_t*>(vp) =
                        pack_half2(acc[mi][ni][0] + b0, acc[mi][ni][1] + b0);
                    *reinterpret_cast<uint32_t*>(vp + (size_t)8 * N) =
                        pack_half2(acc[mi][ni][2] + b1, acc[mi][ni][3] + b1);
                }
            } else {
                const int head = (r0 % CDIM) / HDIM;
                const int d    = r0 % HDIM;
                __half* tb = (cls == 0 ? qroot : kroot)
                           + ((size_t)(blockIdx.z * NHEAD + head) * TDIM) * HDIM;
                #pragma unroll
                for (int ni = 0; ni < 8; ni++) {
                    int cc = col0 + wn * 64 + ni * 8 + tig * 2;
                    __half* p0 = tb + (size_t)cc * HDIM + d;
                    __half* p1 = tb + (size_t)(cc + 1) * HDIM + d;
                    p0[0] = __float2half_rn(acc[mi][ni][0] + b0);
                    p1[0] = __float2half_rn(acc[mi][ni][1] + b0);
                    p0[8] = __float2half_rn(acc[mi][ni][2] + b1);
                    p1[8] = __float2half_rn(acc[mi][ni][3] + b1);
                }
            }
        }
    }
}

// ---------------------------------------------------------------------------
// Flash attention v13: v12 numerics, ldmatrix fragment loads.
// K smem [s][d] pitch 72 halves, V smem [d][s] pitch 72 halves; both
// n-major -> ldmatrix.x4 non-trans yields b0/b1 for ni pairs.
// grid (T/256, H, B), 256 threads, warp tile 32t x 64s / 32t x 64d.
// ---------------------------------------------------------------------------
#define KH_P 72
#define VH_P 72
#define FA_TBLK 256
#define KSTG_H (64 * KH_P)
#define VSTG_H (64 * VH_P)
#define FA_NCHUNK (TDIM / 64)
#define FA_SMEM_BYTES ((3 * KSTG_H + 3 * VSTG_H) * 2 + (TDIM / 2) * 4)
#define LOG2E 1.44269504088896340736f
#define ONES_H2 0x3C003C00u

__global__ __launch_bounds__(256, 1)
void flash_attn_v13(const int* __restrict__ mask)
{
    extern __shared__ __half fsmh[];
    __half*   Ksh   = fsmh;                       // 3 stages [s][d] pitch 72
    __half*   Vsh   = Ksh + 3 * KSTG_H;           // 3 stages [d][s] pitch 72
    uint32_t* maskW = (uint32_t*)(Vsh + 3 * VSTG_H);  // 1024 half2 bias words

    const int b    = blockIdx.z;
    const int h    = blockIdx.y;
    const int tt   = blockIdx.x;
    const int tid  = threadIdx.x;
    const int lane = tid & 31;
    const int warp = tid >> 5;
    const int g    = lane >> 2;
    const int tig  = lane & 3;
    const int tw   = warp * 32;
    const int l16  = lane & 15;
    const int lhi  = lane >> 4;

    const __half* qptr = g_qt + ((size_t)(b * NHEAD + h) * TDIM + tt * FA_TBLK + tw) * HDIM;
    const __half* kptr = g_kt + ((size_t)(b * NHEAD + h) * TDIM) * HDIM;
    const __half* vptr = g_vh + (size_t)b * CDIM * TDIM + (size_t)(h * HDIM) * TDIM;

    const uint32_t kbase0 = smem_u32(Ksh);
    const uint32_t vbase0 = smem_u32(Vsh);

    auto issue = [&](int ch) {
        const uint32_t kb = kbase0 + (unsigned)((ch % 3) * KSTG_H) * 2u;
        const uint32_t vb = vbase0 + (unsigned)((ch % 3) * VSTG_H) * 2u;
        const int s0 = ch * 64;
        #pragma unroll
        for (int l = 0; l < 2; l++) {
            int lin = tid + l * 256;
            int s   = lin >> 3;
            int seg = lin & 7;
            cp_async16(kb + (unsigned)(s * KH_P + seg * 8) * 2u,
                       kptr + (size_t)(s0 + s) * HDIM + seg * 8);
        }
        #pragma unroll
        for (int l = 0; l < 2; l++) {
            int lin = tid + l * 256;
            int d   = lin >> 3;
            int seg = lin & 7;
            cp_async16(vb + (unsigned)(d * VH_P + seg * 8) * 2u,
                       vptr + (size_t)d * TDIM + s0 + seg * 8);
        }
        CP_COMMIT();
    };

    issue(0); issue(1); issue(2);

    // Q fragments (fp16 d-pair words), once per block, from gmem.
    uint32_t Qf[2][4][4];
    #pragma unroll
    for (int mi = 0; mi < 2; mi++) {
        const __half* qrow0 = qptr + (size_t)(mi * 16 + g) * HDIM;
        const __half* qrow1 = qrow0 + (size_t)8 * HDIM;
        #pragma unroll
        for (int kk = 0; kk < 4; kk++) {
            Qf[mi][kk][0] = *reinterpret_cast<const uint32_t*>(qrow0 + (kk * 8 + tig) * 2);
            Qf[mi][kk][1] = *reinterpret_cast<const uint32_t*>(qrow1 + (kk * 8 + tig) * 2);
            Qf[mi][kk][2] = *reinterpret_cast<const uint32_t*>(qrow0 + (kk * 8 + tig + 4) * 2);
            Qf[mi][kk][3] = *reinterpret_cast<const uint32_t*>(qrow1 + (kk * 8 + tig + 4) * 2);
        }
    }

    for (int i = tid; i < TDIM / 2; i += 256) {
        float b0 = (mask[(size_t)b * TDIM + 2 * i]     == 0) ? (-10000.0f * LOG2E) : 0.0f;
        float b1 = (mask[(size_t)b * TDIM + 2 * i + 1] == 0) ? (-10000.0f * LOG2E) : 0.0f;
        maskW[i] = pack_half2(b0, b1);
    }

    float accO[2][8][4];
    #pragma unroll
    for (int mi = 0; mi < 2; mi++)
        #pragma unroll
        for (int ni = 0; ni < 8; ni++)
            #pragma unroll
            for (int r = 0; r < 4; r++) accO[mi][ni][r] = 0.0f;

    float accS[2][4];
    #pragma unroll
    for (int mi = 0; mi < 2; mi++)
        #pragma unroll
        for (int r = 0; r < 4; r++) accS[mi][r] = 0.0f;

    const float sc2f = 0.125f * LOG2E;
    const uint32_t sc2x2 = pack_half2(sc2f, sc2f);
    const uint32_t onesb[2] = { ONES_H2, ONES_H2 };

    for (int kt = 0; kt < FA_NCHUNK; kt++) {
        if      (kt + 2 < FA_NCHUNK) asm volatile("cp.async.wait_group 2;\n");
        else if (kt + 1 < FA_NCHUNK) asm volatile("cp.async.wait_group 1;\n");
        else                         asm volatile("cp.async.wait_group 0;\n");
        __syncthreads();

        const uint32_t kb = kbase0 + (unsigned)((kt % 3) * KSTG_H) * 2u;
        const uint32_t vb = vbase0 + (unsigned)((kt % 3) * VSTG_H) * 2u;
        const uint32_t* mw = maskW + kt * 32;

        // ---- S = Q K^T (fp16 k16), K frags via ldmatrix non-trans ----
        float sacc[2][8][4];
        #pragma unroll
        for (int mi = 0; mi < 2; mi++)
            #pragma unroll
            for (int ni = 0; ni < 8; ni++)
                #pragma unroll
                for (int r = 0; r < 4; r++) sacc[mi][ni][r] = 0.0f;

        #pragma unroll
        for (int kk = 0; kk < 4; kk++) {
            uint32_t bf[8][2];
            #pragma unroll
            for (int p = 0; p < 4; p++) {
                // rows s = p*16 + l16, cols d = kk*16 + lhi*8
                // r0=b0(2p), r1=b0(2p+1), r2=b1(2p), r3=b1(2p+1)
                ldsm_x4(bf[2 * p][0], bf[2 * p + 1][0], bf[2 * p][1], bf[2 * p + 1][1],
                        kb + (unsigned)((p * 16 + l16) * KH_P + kk * 16 + lhi * 8) * 2u);
            }
            #pragma unroll
            for (int mi = 0; mi < 2; mi++)
                #pragma unroll
                for (int ni = 0; ni < 8; ni++)
                    mma_fp16(sacc[mi][ni], Qf[mi][kk], bf[ni]);
        }

        // ---- softmax: half2 pack -> HFMA2 -> ex2.f16x2 ----
        uint32_t pp[2][8][2];
        #pragma unroll
        for (int mi = 0; mi < 2; mi++)
            #pragma unroll
            for (int ni = 0; ni < 8; ni++) {
                uint32_t b2 = mw[ni * 4 + tig];
                uint32_t a01 = pack_half2(sacc[mi][ni][0], sacc[mi][ni][1]);
                uint32_t a23 = pack_half2(sacc[mi][ni][2], sacc[mi][ni][3]);
                pp[mi][ni][0] = h2_fma_ex2(a01, sc2x2, b2);
                pp[mi][ni][1] = h2_fma_ex2(a23, sc2x2, b2);
            }

        // ---- O += P V and row sums += P 1 ; V frags via ldmatrix ----
        #pragma unroll
        for (int kb2 = 0; kb2 < 4; kb2++) {
            uint32_t bf[8][2];
            #pragma unroll
            for (int p = 0; p < 4; p++) {
                // rows d = p*16 + l16, cols s = kb2*16 + lhi*8
                ldsm_x4(bf[2 * p][0], bf[2 * p + 1][0], bf[2 * p][1], bf[2 * p + 1][1],
                        vb + (unsigned)((p * 16 + l16) * VH_P + kb2 * 16 + lhi * 8) * 2u);
            }
            #pragma unroll
            for (int mi = 0; mi < 2; mi++) {
                uint32_t a[4] = { pp[mi][2 * kb2][0],     pp[mi][2 * kb2][1],
                                  pp[mi][2 * kb2 + 1][0], pp[mi][2 * kb2 + 1][1] };
                #pragma unroll
                for (int ni = 0; ni < 8; ni++)
                    mma_fp16(accO[mi][ni], a, bf[ni]);
                mma_fp16(accS[mi], a, onesb);
            }
        }

        __syncthreads();
        if (kt + 3 < FA_NCHUNK) issue(kt + 3);
    }

    // ---- epilogue: normalize, write o as plain fp16 [c][t] ----
    __half* ohp = g_oh + ((size_t)b * CDIM + h * HDIM) * TDIM + tt * FA_TBLK + tw;
    #pragma unroll
    for (int mi = 0; mi < 2; mi++) {
        float il0 = 1.0f / accS[mi][0];   // row g
        float il1 = 1.0f / accS[mi][2];   // row g+8
        #pragma unroll
        for (int ni = 0; ni < 8; ni++) {
            int d = ni * 8 + tig * 2;
            __half* p0 = ohp + (size_t)d * TDIM + mi * 16 + g;
            p0[0]        = __float2half_rn(accO[mi][ni][0] * il0);
            p0[TDIM]     = __float2half_rn(accO[mi][ni][1] * il0);
            p0[8]        = __float2half_rn(accO[mi][ni][2] * il1);
            p0[TDIM + 8] = __float2half_rn(accO[mi][ni][3] * il1);
        }
    }
}

// ---------------------------------------------------------------------------
// kernel_launch (single stream, graph-safe)
// ---------------------------------------------------------------------------
extern "C" void kernel_launch(void* const* d_in, const int* in_sizes, int n_in,
                              void* d_out, int out_size)
{
    const float* x    = (const float*)d_in[0];
    const int*   mask = (const int*)  d_in[1];
    const float* Wqkv = (const float*)d_in[2];
    const float* bqkv = (const float*)d_in[3];
    const float* Wout = (const float*)d_in[4];
    const float* bout = (const float*)d_in[5];
    float*       out  = (float*)d_out;

    __half *qt_p, *kt_p, *vh_p, *oh_p, *xh_p, *wqh_p, *woh_p;
    cudaGetSymbolAddress((void**)&qt_p,  g_qt);
    cudaGetSymbolAddress((void**)&kt_p,  g_kt);
    cudaGetSymbolAddress((void**)&vh_p,  g_vh);
    cudaGetSymbolAddress((void**)&oh_p,  g_oh);
    cudaGetSymbolAddress((void**)&xh_p,  g_xh);
    cudaGetSymbolAddress((void**)&wqh_p, g_wqh);
    cudaGetSymbolAddress((void**)&woh_p, g_woh);

    cudaFuncSetAttribute(gemm_fp16_ldsm<0>,
                         cudaFuncAttributeMaxDynamicSharedMemorySize, GEMM_SMEM_BYTES);
    cudaFuncSetAttribute(gemm_fp16_ldsm<1>,
                         cudaFuncAttributeMaxDynamicSharedMemorySize, GEMM_SMEM_BYTES);
    cudaFuncSetAttribute(flash_attn_v13,
                         cudaFuncAttributeMaxDynamicSharedMemorySize, FA_SMEM_BYTES);

    // 0) pack inputs to fp16 (plain layouts)
    {
        const int nq = QKVROWS * CDIM;
        const int nw = CDIM * CDIM;
        const int nx = BATCH * CDIM * TDIM;
        pack_h_kernel<<<nq / 1024, 256>>>(Wqkv, wqh_p, nq);
        pack_h_kernel<<<nw / 1024, 256>>>(Wout, woh_p, nw);
        pack_h_kernel<<<nx / 1024, 256>>>(x, xh_p, nx);
    }

    // 1) qkv = Wqkv @ x + bqkv  (Q -> qT, K -> kT, V -> vh)
    {
        dim3 grid(TDIM / 128, QKVROWS / 128, BATCH);
        gemm_fp16_ldsm<1><<<grid, 128, GEMM_SMEM_BYTES>>>(
            wqh_p, xh_p, bqkv, nullptr, qt_p, kt_p, vh_p, QKVROWS, TDIM, CDIM);
    }
    // 2) fused flash attention
    {
        dim3 grid(TDIM / FA_TBLK, NHEAD, BATCH);
        flash_attn_v13<<<grid, 256, FA_SMEM_BYTES>>>(mask);
    }
    // 3) out = Wout @ o + bout
    {
        dim3 grid(TDIM / 128, CDIM / 128, BATCH);
        gemm_fp16_ldsm<0><<<grid, 128, GEMM_SMEM_BYTES>>>(
            woh_p, oh_p, bout, out, nullptr, nullptr, nullptr, CDIM, TDIM, CDIM);
    }
}